// round 1
// baseline (speedup 1.0000x reference)
#include <cuda_runtime.h>

// Problem constants (fixed by setup_inputs)
constexpr int B = 4, H = 1024, W = 1024;
constexpr int TX = 32;          // output tile width
constexpr int TY = 16;          // output tile height (2 rows per thread)
constexpr int HX = TX + 10;     // 42: halo tile width
constexpr int HY = TY + 10;     // 26: halo tile height

#define MK 1e30f
// C1P[k][c]: k=0 and k=12 are OOB pads (INF -> weight 0).
// k=1..11 hold (dist - 0.5) for dy = k-1 (dy,dx offsets -5..5), with disk-mask
// zeros replaced by 1e30 so saturatef(coc - c1) == 0 there.
__device__ constexpr float C1P[13][11] = {
  {MK,MK,MK,MK,MK,MK,MK,MK,MK,MK,MK},
  {MK,MK,MK,4.885164807f,4.599019514f,4.5f,4.599019514f,4.885164807f,MK,MK,MK},
  {MK,MK,4.5f,3.972135955f,3.623105626f,3.5f,3.623105626f,3.972135955f,4.5f,MK,MK},
  {MK,4.5f,3.742640687f,3.105551276f,2.662277660f,2.5f,2.662277660f,3.105551276f,3.742640687f,4.5f,MK},
  {4.885164807f,3.972135955f,3.105551276f,2.328427125f,1.736067977f,1.5f,1.736067977f,2.328427125f,3.105551276f,3.972135955f,4.885164807f},
  {4.599019514f,3.623105626f,2.662277660f,1.736067977f,0.914213562f,0.5f,0.914213562f,1.736067977f,2.662277660f,3.623105626f,4.599019514f},
  {4.5f,3.5f,2.5f,1.5f,0.5f,-0.5f,0.5f,1.5f,2.5f,3.5f,4.5f},
  {4.599019514f,3.623105626f,2.662277660f,1.736067977f,0.914213562f,0.5f,0.914213562f,1.736067977f,2.662277660f,3.623105626f,4.599019514f},
  {4.885164807f,3.972135955f,3.105551276f,2.328427125f,1.736067977f,1.5f,1.736067977f,2.328427125f,3.105551276f,3.972135955f,4.885164807f},
  {MK,4.5f,3.742640687f,3.105551276f,2.662277660f,2.5f,2.662277660f,3.105551276f,3.742640687f,4.5f,MK},
  {MK,MK,4.5f,3.972135955f,3.623105626f,3.5f,3.623105626f,3.972135955f,4.5f,MK,MK},
  {MK,MK,MK,4.885164807f,4.599019514f,4.5f,4.599019514f,4.885164807f,MK,MK,MK},
  {MK,MK,MK,MK,MK,MK,MK,MK,MK,MK,MK}
};

__global__ __launch_bounds__(256)
void scatter_render_kernel(const float* __restrict__ x,
                           const float* __restrict__ lens,
                           float* __restrict__ out)
{
    __shared__ float2 s_ec[HY][HX];   // (exp(4*disp), coc)
    __shared__ float2 s_rg[HY][HX];   // (r, g)
    __shared__ float  s_b [HY][HX];   // b

    const int b   = blockIdx.z;
    const int gx0 = blockIdx.x * TX;
    const int gy0 = blockIdx.y * TY;

    const float scale = fabsf(lens[b]);
    const float* __restrict__ xb = x + (size_t)b * 4 * H * W;
    const float* __restrict__ pr = xb;
    const float* __restrict__ pg = xb + H * W;
    const float* __restrict__ pb = xb + 2 * H * W;
    const float* __restrict__ pd = xb + 3 * H * W;

    // ---- cooperative halo-tile fill (with edge clamp) ----
    const int tid = threadIdx.y * TX + threadIdx.x;
    for (int idx = tid; idx < HY * HX; idx += 256) {
        int yy = idx / HX;
        int xx = idx - yy * HX;
        int sy = gy0 + yy - 5; sy = min(max(sy, 0), H - 1);
        int sx = gx0 + xx - 5; sx = min(max(sx, 0), W - 1);
        int o  = sy * W + sx;
        float d  = pd[o];
        float es = __expf(4.0f * d);
        float cc = scale * fabsf(d);
        s_ec[yy][xx] = make_float2(es, cc);
        s_rg[yy][xx] = make_float2(pr[o], pg[o]);
        s_b [yy][xx] = pb[o];
    }
    __syncthreads();

    // ---- main gather: each thread owns 2 vertically adjacent outputs ----
    const int tx = threadIdx.x;
    const int ry = 2 * threadIdx.y;        // local output row 0 of the pair

    const float ed0 = s_ec[ry + 5][tx + 5].x;   // exp(4*disp_dst) for row ry
    const float ed1 = s_ec[ry + 6][tx + 5].x;   // ... for row ry+1

    float nr0 = 0.f, ng0 = 0.f, nb0 = 0.f, nd0 = 0.f;
    float nr1 = 0.f, ng1 = 0.f, nb1 = 0.f, nd1 = 0.f;

    #pragma unroll
    for (int sr = 0; sr < 12; ++sr) {       // union of both outputs' 11 rows
        #pragma unroll
        for (int sc = 0; sc < 11; ++sc) {
            const float2 ec = s_ec[ry + sr][tx + sc];
            const float2 rg = s_rg[ry + sr][tx + sc];
            const float  bb = s_b [ry + sr][tx + sc];
            // out0 sees this source at dy = sr, out1 at dy = sr-1
            const float w0 = __saturatef(ec.y - C1P[sr + 1][sc]);
            const float w1 = __saturatef(ec.y - C1P[sr    ][sc]);
            const float wo0 = __fdividef(w0 * ec.x, ec.x + ed0);
            const float wo1 = __fdividef(w1 * ec.x, ec.x + ed1);
            nr0 += wo0 * rg.x;  ng0 += wo0 * rg.y;  nb0 += wo0 * bb;  nd0 += wo0;
            nr1 += wo1 * rg.x;  ng1 += wo1 * rg.y;  nb1 += wo1 * bb;  nd1 += wo1;
        }
    }

    const int gx = gx0 + tx;
    const int gy = gy0 + ry;
    float* __restrict__ ob = out + (size_t)b * 3 * H * W;
    const float inv0 = __fdividef(1.0f, nd0 + 1e-8f);
    const float inv1 = __fdividef(1.0f, nd1 + 1e-8f);
    const int o0 = gy * W + gx;
    const int o1 = o0 + W;
    ob[o0]             = nr0 * inv0;
    ob[H * W + o0]     = ng0 * inv0;
    ob[2 * H * W + o0] = nb0 * inv0;
    ob[o1]             = nr1 * inv1;
    ob[H * W + o1]     = ng1 * inv1;
    ob[2 * H * W + o1] = nb1 * inv1;
}

extern "C" void kernel_launch(void* const* d_in, const int* in_sizes, int n_in,
                              void* d_out, int out_size)
{
    const float* x    = (const float*)d_in[0];
    const float* lens = (const float*)d_in[1];
    float* out        = (float*)d_out;

    dim3 block(TX, TY / 2, 1);              // 32 x 8 = 256 threads
    dim3 grid(W / TX, H / TY, B);           // 32 x 64 x 4
    scatter_render_kernel<<<grid, block>>>(x, lens, out);
}